// round 10
// baseline (speedup 1.0000x reference)
#include <cuda_runtime.h>
#include <cstdint>

// Problem shape (fixed by the reference): B=8, S=512, V=32000, M=32, PAD_ID=1
// NOTE: jax without x64 silently makes "int64" inputs int32 — a and mask are int32.
#define BB 8
#define SS 512
#define VV 32000
#define MM 32
#define PAD_ID 1

#define ROWS (BB * SS)          // 4096
#define THREADS 512             // 16 warps/block
#define ROWS_PER_BLOCK 16
#define NBLOCKS (ROWS / ROWS_PER_BLOCK)   // 256
// 32 consecutive partials per batch element (256 / 8).

// Scratch (device-side allocation is forbidden -> __device__ globals).
__device__ float g_partials[NBLOCKS];
__device__ unsigned int g_done = 0;   // reset to 0 by the last block each run

// One warp per (b,s) row; lane j handles mask[b,s,j].
// logp(b,s) = logits[b,s,a] - log( sum_{j: mask_j>0} exp(logits[b,s,mask_j]) )
// The scattered logits gather goes through cp.async (LDGSTS) instead of LDG:
// LDGSTS has no observed outstanding-depth cap, so the per-SM miss pool that
// throttles divergent LDG streams is bypassed.
__global__ void __launch_bounds__(THREADS) masked_logp_kernel(
    const float* __restrict__ logits,   // [B,S,V] f32
    const int* __restrict__ a,          // [B,S]   i32
    const int* __restrict__ mask,       // [B,S,M] i32
    float* __restrict__ out)            // [B]     f32
{
    __shared__ float s_g[ROWS_PER_BLOCK][32];   // gathered logits, per warp
    __shared__ float s_logp[ROWS_PER_BLOCK];
    __shared__ bool  s_last;

    const int warp = threadIdx.x >> 5;
    const int lane = threadIdx.x & 31;
    const int row  = blockIdx.x * ROWS_PER_BLOCK + warp;

    const float* __restrict__ lrow = logits + (size_t)row * VV;

    // Action-token chain (lane 0), overlaps the gather round.
    const int ai = (lane == 0) ? __ldg(a + row) : 0;
    float la = 0.0f;
    bool take = false;
    if (lane == 0 && ai != PAD_ID) {
        take = true;
        la = __ldcs(lrow + ai);
    }

    // Mask ids: coalesced 128B row per warp.
    const int mid = __ldg(mask + (size_t)row * MM + lane);
    const bool valid = (mid > 0);

    // Scattered 4B gather via cp.async into this lane's smem slot.
    // Invalid lanes fetch lrow[0] (always in-bounds) and are masked below.
    {
        const float* src = lrow + (valid ? mid : 0);
        const uint32_t dst =
            (uint32_t)__cvta_generic_to_shared(&s_g[warp][lane]);
        asm volatile("cp.async.ca.shared.global [%0], [%1], 4;\n"
                     :: "r"(dst), "l"(src) : "memory");
        asm volatile("cp.async.commit_group;\n" ::: "memory");
        asm volatile("cp.async.wait_group 0;\n" ::: "memory");
    }
    __syncwarp();

    float g = valid ? s_g[warp][lane] : -__int_as_float(0x7f800000); // -inf

    // Warp max over gathered logits.
    float m = g;
    #pragma unroll
    for (int o = 16; o > 0; o >>= 1)
        m = fmaxf(m, __shfl_xor_sync(0xffffffffu, m, o));

    // Warp sum of exp(g - m) over valid lanes.
    float e = valid ? __expf(g - m) : 0.0f;
    #pragma unroll
    for (int o = 16; o > 0; o >>= 1)
        e += __shfl_xor_sync(0xffffffffu, e, o);

    if (lane == 0)
        s_logp[warp] = take ? (la - (m + __logf(e))) : 0.0f;

    __syncthreads();

    // Warp 0: reduce 16 per-row values -> block partial; detect last block.
    if (warp == 0) {
        float v = (lane < ROWS_PER_BLOCK) ? s_logp[lane] : 0.0f;
        #pragma unroll
        for (int o = 8; o > 0; o >>= 1)
            v += __shfl_xor_sync(0xffffffffu, v, o);
        if (lane == 0) {
            g_partials[blockIdx.x] = v;
            __threadfence();
            const unsigned int prev = atomicAdd(&g_done, 1u);
            s_last = (prev == NBLOCKS - 1);
        }
    }
    __syncthreads();

    // Last block folds all 256 partials into out[8] and resets the counter.
    if (s_last) {
        __threadfence();  // acquire: make all g_partials writes visible
        const int tid = threadIdx.x;
        if (tid < NBLOCKS) {
            float v = g_partials[tid];
            // 32 consecutive partials per batch element == one full warp.
            #pragma unroll
            for (int o = 16; o > 0; o >>= 1)
                v += __shfl_xor_sync(0xffffffffu, v, o);
            if (lane == 0)
                out[tid >> 5] = v;
        }
        if (tid == 0)
            g_done = 0;   // deterministic across graph replays
    }
}

extern "C" void kernel_launch(void* const* d_in, const int* in_sizes, int n_in,
                              void* d_out, int out_size) {
    const float* logits = (const float*)d_in[0];  // [8,512,32000] f32
    const int* a        = (const int*)d_in[1];    // [8,512]       i32
    const int* mask     = (const int*)d_in[2];    // [8,512,32]    i32
    float* out = (float*)d_out;                   // [8]           f32

    masked_logp_kernel<<<NBLOCKS, THREADS>>>(logits, a, mask, out);
}

// round 11
// speedup vs baseline: 1.3529x; 1.3529x over previous
#include <cuda_runtime.h>
#include <cstdint>

// Problem shape (fixed by the reference): B=8, S=512, V=32000, M=32, PAD_ID=1
// NOTE: jax without x64 silently makes "int64" inputs int32 — a and mask are int32.
#define BB 8
#define SS 512
#define VV 32000
#define MM 32
#define PAD_ID 1

#define ROWS (BB * SS)          // 4096
#define RPW 4                   // rows per warp (prefetch pipeline depth)
#define WARPS_PER_BLOCK 8
#define THREADS (WARPS_PER_BLOCK * 32)           // 256
#define ROWS_PER_BLOCK (WARPS_PER_BLOCK * RPW)   // 32
#define NBLOCKS (ROWS / ROWS_PER_BLOCK)          // 128
// 16 consecutive partials per batch element (128 / 8).

// Scratch (device-side allocation is forbidden -> __device__ globals).
__device__ float g_partials[NBLOCKS];
__device__ unsigned int g_done = 0;   // reset to 0 by the last block each run

#define NEG_INF (-__int_as_float(0x7f800000))

// Each warp owns RPW consecutive rows. All gather lines are L2-prefetched up
// front; rows are then consumed sequentially so later rows' LDGs land on
// L2 hits (~250cyc) instead of DRAM misses (~600cyc), turning the per-SM
// miss-tracking slots over faster.
__global__ void __launch_bounds__(THREADS) masked_logp_kernel(
    const float* __restrict__ logits,   // [B,S,V] f32
    const int* __restrict__ a,          // [B,S]   i32
    const int* __restrict__ mask,       // [B,S,M] i32
    float* __restrict__ out)            // [B]     f32
{
    __shared__ float s_logp[WARPS_PER_BLOCK];
    __shared__ bool  s_last;

    const int warp = threadIdx.x >> 5;
    const int lane = threadIdx.x & 31;
    const int base_row = blockIdx.x * ROWS_PER_BLOCK + warp * RPW;

    // --- Phase 1: all index loads + prefetches, maximum distance ---

    // Mask ids for the 4 rows (each a coalesced 128B row).
    int mid[RPW];
    #pragma unroll
    for (int r = 0; r < RPW; r++)
        mid[r] = __ldg(mask + (size_t)(base_row + r) * MM + lane);

    // Action ids: lane r (<RPW) owns row base_row+r.
    const int my_row = base_row + (lane & (RPW - 1));
    const int ai   = (lane < RPW) ? __ldg(a + my_row) : PAD_ID;
    const int take = (lane < RPW) && (ai != PAD_ID);
    // PAD_ID=1 is a valid index, so load unconditionally on lanes<RPW.
    const float la = (lane < RPW)
        ? __ldg(logits + (size_t)my_row * VV + ai) : 0.0f;

    // Gather pointers + L2 prefetch for all RPW*32 lines.
    const float* gp[RPW];
    bool valid[RPW];
    #pragma unroll
    for (int r = 0; r < RPW; r++) {
        valid[r] = (mid[r] > 0);
        gp[r] = logits + (size_t)(base_row + r) * VV + (valid[r] ? mid[r] : 0);
        if (valid[r])
            asm volatile("prefetch.global.L2 [%0];" :: "l"(gp[r]));
    }

    // --- Phase 2: consume rows sequentially (prefetch distance grows per row) ---
    float acc = 0.0f;
    #pragma unroll
    for (int r = 0; r < RPW; r++) {
        const float g = valid[r] ? __ldg(gp[r]) : NEG_INF;

        float m = g;
        #pragma unroll
        for (int o = 16; o > 0; o >>= 1)
            m = fmaxf(m, __shfl_xor_sync(0xffffffffu, m, o));

        float e = valid[r] ? __expf(g - m) : 0.0f;
        #pragma unroll
        for (int o = 16; o > 0; o >>= 1)
            e += __shfl_xor_sync(0xffffffffu, e, o);

        const float la_r   = __shfl_sync(0xffffffffu, la, r);
        const int   take_r = __shfl_sync(0xffffffffu, take, r);
        if (take_r)
            acc += la_r - (m + __logf(e));
    }

    if (lane == 0)
        s_logp[warp] = acc;

    __syncthreads();

    // Warp 0: reduce per-warp sums -> block partial; detect last block.
    if (warp == 0) {
        float v = (lane < WARPS_PER_BLOCK) ? s_logp[lane] : 0.0f;
        #pragma unroll
        for (int o = 4; o > 0; o >>= 1)
            v += __shfl_xor_sync(0xffffffffu, v, o);
        if (lane == 0) {
            g_partials[blockIdx.x] = v;
            __threadfence();
            const unsigned int prev = atomicAdd(&g_done, 1u);
            s_last = (prev == NBLOCKS - 1);
        }
    }
    __syncthreads();

    // Last block folds all 128 partials into out[8] and resets the counter.
    if (s_last) {
        __threadfence();  // acquire: make all g_partials writes visible
        const int tid = threadIdx.x;
        if (tid < NBLOCKS) {
            float v = g_partials[tid];
            // 16 consecutive partials per batch element; segments within a warp.
            #pragma unroll
            for (int o = 8; o > 0; o >>= 1)
                v += __shfl_down_sync(0xffffffffu, v, o, 16);
            if ((tid & 15) == 0)
                out[tid >> 4] = v;
        }
        if (tid == 0)
            g_done = 0;   // deterministic across graph replays
    }
}

extern "C" void kernel_launch(void* const* d_in, const int* in_sizes, int n_in,
                              void* d_out, int out_size) {
    const float* logits = (const float*)d_in[0];  // [8,512,32000] f32
    const int* a        = (const int*)d_in[1];    // [8,512]       i32
    const int* mask     = (const int*)d_in[2];    // [8,512,32]    i32
    float* out = (float*)d_out;                   // [8]           f32

    masked_logp_kernel<<<NBLOCKS, THREADS>>>(logits, a, mask, out);
}